// round 4
// baseline (speedup 1.0000x reference)
#include <cuda_runtime.h>
#include <cstdint>

// ============================================================================
// Problem constants
// ============================================================================
#define M_TOTAL 8192          // 4 * 2048
#define N_TOTAL 4096          // out features
#define K_TOTAL 4096          // in features

#define BM 128                // CTA tile M
#define BN 128                // CTA tile N
#define BK 32                 // K per stage (32 tf32 = 128 bytes/row -> SW128)
#define NSTAGE 4
#define NKIT (K_TOTAL / BK)   // 128 K-iterations

#define A_STAGE_BYTES (BM * BK * 4)                 // 16384
#define B_STAGE_BYTES (BN * BK * 4)                 // 16384
#define STAGE_BYTES   (A_STAGE_BYTES + B_STAGE_BYTES)   // 32768
#define SMEM_BYTES    (NSTAGE * STAGE_BYTES)        // 131072

#define THREADS 256           // 8 warps: 4 (M) x 2 (N); warp tile 32 x 64

#define SMEM_SWIZZLE_128B(byte_offset) \
    ((byte_offset) ^ (((byte_offset) >> 3) & 0x70))

// ============================================================================
// Scratch (no runtime allocation allowed -> __device__ globals)
// ============================================================================
__device__ float g_W[(size_t)N_TOTAL * K_TOTAL];   // dequantized W, tf32-rounded
__device__ float g_X[(size_t)M_TOTAL * K_TOTAL];   // x, tf32-rounded

// ============================================================================
// PTX helpers (all baseline PTX, legal under compute_103: no tcgen05 / "a" feats)
// ============================================================================
__device__ __forceinline__ uint32_t smem_u32(const void* p) {
    uint32_t a;
    asm("{ .reg .u64 t; cvta.to.shared.u64 t, %1; cvt.u32.u64 %0, t; }" : "=r"(a) : "l"(p));
    return a;
}

__device__ __forceinline__ float to_tf32(float f) {
    uint32_t u;
    asm("cvt.rna.tf32.f32 %0, %1;" : "=r"(u) : "f"(f));
    return __uint_as_float(u);
}

__device__ __forceinline__ void cp_async16(uint32_t dst, const float* src) {
    asm volatile("cp.async.cg.shared.global [%0], [%1], 16;"
                 :: "r"(dst), "l"(__cvta_generic_to_global(src)) : "memory");
}
__device__ __forceinline__ void cp_commit() {
    asm volatile("cp.async.commit_group;" ::: "memory");
}
__device__ __forceinline__ void cp_wait3() {
    asm volatile("cp.async.wait_group 3;" ::: "memory");
}

// ldmatrix x4 (b16): a 16x8 tf32 tile viewed as 16x16 b16 decomposes into four
// 8x8 b16 sub-tiles that land exactly as {a0,a1,a2,a3} of mma.m16n8k8.tf32.
// The same instruction on the n-major B layout yields {b0,b1} for two n8 tiles.
__device__ __forceinline__ void ldsm_x4(uint32_t& r0, uint32_t& r1, uint32_t& r2,
                                        uint32_t& r3, uint32_t addr) {
    asm volatile("ldmatrix.sync.aligned.m8n8.x4.shared.b16 {%0,%1,%2,%3}, [%4];"
                 : "=r"(r0), "=r"(r1), "=r"(r2), "=r"(r3) : "r"(addr));
}

__device__ __forceinline__ void mma_tf32(float* c, const uint32_t* a, const uint32_t* b) {
    asm volatile(
        "mma.sync.aligned.m16n8k8.row.col.f32.tf32.tf32.f32 "
        "{%0,%1,%2,%3}, {%4,%5,%6,%7}, {%8,%9}, {%0,%1,%2,%3};"
        : "+f"(c[0]), "+f"(c[1]), "+f"(c[2]), "+f"(c[3])
        : "r"(a[0]), "r"(a[1]), "r"(a[2]), "r"(a[3]), "r"(b[0]), "r"(b[1]));
}

// ============================================================================
// Kernel 1: dequantize W = tf32(centroids[labels]),  W[n,k] layout
// ============================================================================
__global__ void __launch_bounds__(256) dequant_kernel(
    const float* __restrict__ centroids, const int* __restrict__ labels) {
    __shared__ float c[256];
    int t = threadIdx.x;
    c[t] = to_tf32(centroids[t]);
    __syncthreads();
    size_t i = ((size_t)blockIdx.x * 256 + t) * 4;
    int4 l = *reinterpret_cast<const int4*>(labels + i);
    float4 w;
    w.x = c[l.x]; w.y = c[l.y]; w.z = c[l.z]; w.w = c[l.w];
    *reinterpret_cast<float4*>(g_W + i) = w;
}

// ============================================================================
// Kernel 2: round x to tf32 (rna rounding on both operands ~halves GEMM error)
// ============================================================================
__global__ void __launch_bounds__(256) cvt_x_kernel(const float* __restrict__ x) {
    size_t i = ((size_t)blockIdx.x * 256 + threadIdx.x) * 4;
    float4 v = *reinterpret_cast<const float4*>(x + i);
    float4 o;
    o.x = to_tf32(v.x); o.y = to_tf32(v.y); o.z = to_tf32(v.z); o.w = to_tf32(v.w);
    *reinterpret_cast<float4*>(g_X + i) = o;
}

// ============================================================================
// Kernel 3: GEMM  y[m,n] = sum_k X[m,k] * W[n,k] + bias[n]
//   SM80-style 4-stage cp.async pipeline, ldmatrix fragments (one k8 ahead),
//   mma.sync tf32, bias fused in epilogue.
// ============================================================================
__global__ void __launch_bounds__(THREADS, 1) gemm_kernel(
    const float* __restrict__ bias, float* __restrict__ out) {
    extern __shared__ char smem[];
    const uint32_t sb = smem_u32(smem);
    const int tid  = threadIdx.x;
    const int lane = tid & 31;
    const int warp = tid >> 5;
    const int wm = warp & 3;         // warp M index (0..3), tile 32 rows
    const int wn = warp >> 2;        // warp N index (0..1), tile 64 cols

    const float* gA = g_X + (size_t)blockIdx.y * BM * K_TOTAL;
    const float* gB = g_W + (size_t)blockIdx.x * BN * K_TOTAL;

    // ---- precomputed ldmatrix address components (swizzle = XOR bits[6:4]) ----
    const uint32_t xorv = (uint32_t)(lane & 7) << 4;
    // A: per m16 tile mi: lane t -> row = wm*32 + mi*16 + (t&15), half = (t>>4)&1
    uint32_t aRow[2];
    const uint32_t aHx = ((lane >> 4) & 1) * 16;
    #pragma unroll
    for (int mi = 0; mi < 2; mi++)
        aRow[mi] = (uint32_t)(wm * 32 + mi * 16 + (lane & 15)) * 128;
    // B: per n16 group nt: lane t -> n = wn*64 + nt*16 + (t&7) + ((t>>4)&1)*8,
    //    k-half = (t>>3)&1
    uint32_t bRow[4];
    const uint32_t bHx = ((lane >> 3) & 1) * 16;
    #pragma unroll
    for (int nt = 0; nt < 4; nt++)
        bRow[nt] = (uint32_t)(wn * 64 + nt * 16 + (lane & 7) + ((lane >> 4) & 1) * 8) * 128;

    float acc[2][8][4];
    #pragma unroll
    for (int mi = 0; mi < 2; mi++)
        #pragma unroll
        for (int ni = 0; ni < 8; ni++)
            #pragma unroll
            for (int e = 0; e < 4; e++) acc[mi][ni][e] = 0.f;

    // ---- stage loader: 4 A-chunks + 4 B-chunks (16B each) per thread ----
    auto load_stage = [&](int s, int kt) {
        const uint32_t aBase = sb + s * STAGE_BYTES;
        const uint32_t bBase = aBase + A_STAGE_BYTES;
        const float* pA = gA + kt * BK;
        const float* pB = gB + kt * BK;
        #pragma unroll
        for (int i = 0; i < 4; i++) {        // 128 rows x 8 chunks = 1024 / 256 thr
            int idx = i * 256 + tid;
            int r = idx >> 3, j = idx & 7;
            cp_async16(aBase + SMEM_SWIZZLE_128B(r * 128 + j * 16),
                       pA + (size_t)r * K_TOTAL + j * 4);
        }
        #pragma unroll
        for (int i = 0; i < 4; i++) {
            int idx = i * 256 + tid;
            int r = idx >> 3, j = idx & 7;
            cp_async16(bBase + SMEM_SWIZZLE_128B(r * 128 + j * 16),
                       pB + (size_t)r * K_TOTAL + j * 4);
        }
    };

    // fragment fetch for one k8 slice q of the stage at (aBase,bBase)
    uint32_t A[2][2][4], B[2][8][2];   // double-buffered fragments
    auto fetch_frags = [&](int buf, uint32_t aBase, uint32_t bBase, int q) {
        #pragma unroll
        for (int mi = 0; mi < 2; mi++)
            ldsm_x4(A[buf][mi][0], A[buf][mi][1], A[buf][mi][2], A[buf][mi][3],
                    aBase + aRow[mi] + ((((uint32_t)q << 5) | aHx) ^ xorv));
        #pragma unroll
        for (int nt = 0; nt < 4; nt++)
            ldsm_x4(B[buf][2 * nt][0], B[buf][2 * nt][1],
                    B[buf][2 * nt + 1][0], B[buf][2 * nt + 1][1],
                    bBase + bRow[nt] + ((((uint32_t)q << 5) | bHx) ^ xorv));
    };
    auto do_mmas = [&](int buf) {
        #pragma unroll
        for (int mi = 0; mi < 2; mi++)
            #pragma unroll
            for (int ni = 0; ni < 8; ni++)
                mma_tf32(acc[mi][ni], A[buf][mi], B[buf][ni]);
    };

    // ---- prologue: stages 0..2 in flight ----
    #pragma unroll
    for (int s = 0; s < NSTAGE - 1; s++) { load_stage(s, s); cp_commit(); }

    // ---- main loop (fragments pipelined one k8 ahead within the stage) ----
    #pragma unroll 1
    for (int kt = 0; kt < NKIT; kt++) {
        if (kt + NSTAGE - 1 < NKIT) load_stage((kt + NSTAGE - 1) & (NSTAGE - 1),
                                               kt + NSTAGE - 1);
        cp_commit();              // always commit (possibly empty) to keep count
        cp_wait3();               // stage kt's group complete
        __syncthreads();

        const uint32_t aBase = sb + (kt & (NSTAGE - 1)) * STAGE_BYTES;
        const uint32_t bBase = aBase + A_STAGE_BYTES;

        fetch_frags(0, aBase, bBase, 0);
        #pragma unroll
        for (int q = 0; q < 3; q++) {
            fetch_frags((q + 1) & 1, aBase, bBase, q + 1);  // prefetch next k8
            do_mmas(q & 1);                                  // consume current
        }
        do_mmas(3 & 1);
        __syncthreads();          // compute done before this buffer is refilled
    }

    // ---- epilogue: + bias, write float2 pairs ----
    const int g  = lane >> 2;     // group row
    const int tg = lane & 3;      // col pair
    #pragma unroll
    for (int mi = 0; mi < 2; mi++) {
        const int m0 = blockIdx.y * BM + wm * 32 + mi * 16 + g;
        #pragma unroll
        for (int ni = 0; ni < 8; ni++) {
            const int n = blockIdx.x * BN + wn * 64 + ni * 8 + tg * 2;
            float2 bv = *reinterpret_cast<const float2*>(bias + n);
            float2 v0 = { acc[mi][ni][0] + bv.x, acc[mi][ni][1] + bv.y };
            float2 v1 = { acc[mi][ni][2] + bv.x, acc[mi][ni][3] + bv.y };
            *reinterpret_cast<float2*>(out + (size_t)m0 * N_TOTAL + n) = v0;
            *reinterpret_cast<float2*>(out + (size_t)(m0 + 8) * N_TOTAL + n) = v1;
        }
    }
}

// ============================================================================
// Launch (graph-capturable: kernel launches only)
// ============================================================================
extern "C" void kernel_launch(void* const* d_in, const int* in_sizes, int n_in,
                              void* d_out, int out_size) {
    const float* x         = (const float*)d_in[0];   // 4*2048*4096 f32
    const float* centroids = (const float*)d_in[1];   // 256 f32
    const int*   labels    = (const int*)d_in[2];     // 4096*4096 i32
    const float* bias      = (const float*)d_in[3];   // 4096 f32
    float* out = (float*)d_out;                       // 8192*4096 f32

    cudaFuncSetAttribute(gemm_kernel, cudaFuncAttributeMaxDynamicSharedMemorySize,
                         SMEM_BYTES);

    dequant_kernel<<<(N_TOTAL * K_TOTAL) / 1024, 256>>>(centroids, labels);
    cvt_x_kernel<<<(M_TOTAL * K_TOTAL) / 1024, 256>>>(x);
    gemm_kernel<<<dim3(N_TOTAL / BN, M_TOTAL / BM), THREADS, SMEM_BYTES>>>(bias, out);
}

// round 7
// speedup vs baseline: 1.3383x; 1.3383x over previous
#include <cuda_runtime.h>
#include <cstdint>

// ============================================================================
// Problem constants
// ============================================================================
#define M_TOTAL 8192          // 4 * 2048
#define N_TOTAL 4096          // out features
#define K_TOTAL 4096          // in features

#define BM 128                // CTA tile M
#define BN 128                // CTA tile N
#define BK 32                 // K per stage (32 tf32 = 128 bytes/row -> SW128)
#define NSTAGE 3
#define NKIT (K_TOTAL / BK)   // 128 K-iterations

#define A_STAGE_BYTES (BM * BK * 4)                 // 16384
#define B_STAGE_BYTES (BN * BK * 4)                 // 16384
#define STAGE_BYTES   (A_STAGE_BYTES + B_STAGE_BYTES)   // 32768
#define SMEM_BYTES    (NSTAGE * STAGE_BYTES)        // 98304 -> 2 CTAs/SM

#define THREADS 256           // 8 warps: 4 (M) x 2 (N); warp tile 32 x 64

#define SMEM_SWIZZLE_128B(byte_offset) \
    ((byte_offset) ^ (((byte_offset) >> 3) & 0x70))

// ============================================================================
// Scratch (no runtime allocation allowed -> __device__ globals)
// ============================================================================
__device__ float g_W[(size_t)N_TOTAL * K_TOTAL];   // dequantized W, tf32-rounded
__device__ float g_X[(size_t)M_TOTAL * K_TOTAL];   // x, tf32-rounded

// ============================================================================
// PTX helpers (all baseline PTX, legal under compute_103)
// ============================================================================
__device__ __forceinline__ uint32_t smem_u32(const void* p) {
    uint32_t a;
    asm("{ .reg .u64 t; cvta.to.shared.u64 t, %1; cvt.u32.u64 %0, t; }" : "=r"(a) : "l"(p));
    return a;
}

__device__ __forceinline__ float to_tf32(float f) {
    uint32_t u;
    asm("cvt.rna.tf32.f32 %0, %1;" : "=r"(u) : "f"(f));
    return __uint_as_float(u);
}

__device__ __forceinline__ void cp_async16(uint32_t dst, const float* src) {
    asm volatile("cp.async.cg.shared.global [%0], [%1], 16;"
                 :: "r"(dst), "l"(__cvta_generic_to_global(src)) : "memory");
}
__device__ __forceinline__ void cp_commit() {
    asm volatile("cp.async.commit_group;" ::: "memory");
}
__device__ __forceinline__ void cp_wait1() {
    asm volatile("cp.async.wait_group 1;" ::: "memory");
}

// ldmatrix x4 (b16): a 16x8 tf32 tile viewed as 16x16 b16 decomposes into four
// 8x8 b16 sub-tiles landing exactly as {a0..a3} of mma.m16n8k8.tf32; on the
// n-major B layout the same instruction yields {b0,b1} for two n8 tiles.
__device__ __forceinline__ void ldsm_x4(uint32_t& r0, uint32_t& r1, uint32_t& r2,
                                        uint32_t& r3, uint32_t addr) {
    asm volatile("ldmatrix.sync.aligned.m8n8.x4.shared.b16 {%0,%1,%2,%3}, [%4];"
                 : "=r"(r0), "=r"(r1), "=r"(r2), "=r"(r3) : "r"(addr));
}

__device__ __forceinline__ void mma_tf32(float* c, const uint32_t* a, const uint32_t* b) {
    asm volatile(
        "mma.sync.aligned.m16n8k8.row.col.f32.tf32.tf32.f32 "
        "{%0,%1,%2,%3}, {%4,%5,%6,%7}, {%8,%9}, {%0,%1,%2,%3};"
        : "+f"(c[0]), "+f"(c[1]), "+f"(c[2]), "+f"(c[3])
        : "r"(a[0]), "r"(a[1]), "r"(a[2]), "r"(a[3]), "r"(b[0]), "r"(b[1]));
}

// ============================================================================
// Kernel 1: dequantize W = tf32(centroids[labels]),  W[n,k] layout
// ============================================================================
__global__ void __launch_bounds__(256) dequant_kernel(
    const float* __restrict__ centroids, const int* __restrict__ labels) {
    __shared__ float c[256];
    int t = threadIdx.x;
    c[t] = to_tf32(centroids[t]);
    __syncthreads();
    size_t i = ((size_t)blockIdx.x * 256 + t) * 4;
    int4 l = *reinterpret_cast<const int4*>(labels + i);
    float4 w;
    w.x = c[l.x]; w.y = c[l.y]; w.z = c[l.z]; w.w = c[l.w];
    *reinterpret_cast<float4*>(g_W + i) = w;
}

// ============================================================================
// Kernel 2: round x to tf32 (rna rounding on both operands ~halves GEMM error)
// ============================================================================
__global__ void __launch_bounds__(256) cvt_x_kernel(const float* __restrict__ x) {
    size_t i = ((size_t)blockIdx.x * 256 + threadIdx.x) * 4;
    float4 v = *reinterpret_cast<const float4*>(x + i);
    float4 o;
    o.x = to_tf32(v.x); o.y = to_tf32(v.y); o.z = to_tf32(v.z); o.w = to_tf32(v.w);
    *reinterpret_cast<float4*>(g_X + i) = o;
}

// ============================================================================
// Kernel 3: GEMM  y[m,n] = sum_k X[m,k] * W[n,k] + bias[n]
//   3-stage cp.async pipeline, ONE __syncthreads per K-iter, 2 CTAs/SM.
// ============================================================================
__global__ void __launch_bounds__(THREADS, 2) gemm_kernel(
    const float* __restrict__ bias, float* __restrict__ out) {
    extern __shared__ char smem[];
    const uint32_t sb = smem_u32(smem);
    const int tid  = threadIdx.x;
    const int lane = tid & 31;
    const int warp = tid >> 5;
    const int wm = warp & 3;         // warp M index (0..3), tile 32 rows
    const int wn = warp >> 2;        // warp N index (0..1), tile 64 cols

    const float* gA = g_X + (size_t)blockIdx.y * BM * K_TOTAL;
    const float* gB = g_W + (size_t)blockIdx.x * BN * K_TOTAL;

    // ---- precomputed ldmatrix address components (swizzle = XOR bits[6:4]) ----
    const uint32_t xorv = (uint32_t)(lane & 7) << 4;
    // A: per m16 tile mi: lane t -> row = wm*32 + mi*16 + (t&15), half = (t>>4)&1
    uint32_t aRow[2];
    const uint32_t aHx = ((lane >> 4) & 1) * 16;
    #pragma unroll
    for (int mi = 0; mi < 2; mi++)
        aRow[mi] = (uint32_t)(wm * 32 + mi * 16 + (lane & 15)) * 128;
    // B: per n16 group nt: lane t -> n = wn*64 + nt*16 + (t&7) + ((t>>4)&1)*8,
    //    k-half = (t>>3)&1
    uint32_t bRow[4];
    const uint32_t bHx = ((lane >> 3) & 1) * 16;
    #pragma unroll
    for (int nt = 0; nt < 4; nt++)
        bRow[nt] = (uint32_t)(wn * 64 + nt * 16 + (lane & 7) + ((lane >> 4) & 1) * 8) * 128;

    float acc[2][8][4];
    #pragma unroll
    for (int mi = 0; mi < 2; mi++)
        #pragma unroll
        for (int ni = 0; ni < 8; ni++)
            #pragma unroll
            for (int e = 0; e < 4; e++) acc[mi][ni][e] = 0.f;

    // ---- stage loader: 4 A-chunks + 4 B-chunks (16B each) per thread ----
    auto load_stage = [&](int s, int kt) {
        const uint32_t aBase = sb + s * STAGE_BYTES;
        const uint32_t bBase = aBase + A_STAGE_BYTES;
        const float* pA = gA + kt * BK;
        const float* pB = gB + kt * BK;
        #pragma unroll
        for (int i = 0; i < 4; i++) {        // 128 rows x 8 chunks = 1024 / 256 thr
            int idx = i * 256 + tid;
            int r = idx >> 3, j = idx & 7;
            cp_async16(aBase + SMEM_SWIZZLE_128B(r * 128 + j * 16),
                       pA + (size_t)r * K_TOTAL + j * 4);
        }
        #pragma unroll
        for (int i = 0; i < 4; i++) {
            int idx = i * 256 + tid;
            int r = idx >> 3, j = idx & 7;
            cp_async16(bBase + SMEM_SWIZZLE_128B(r * 128 + j * 16),
                       pB + (size_t)r * K_TOTAL + j * 4);
        }
    };

    // ---- prologue: stages 0..1 in flight ----
    #pragma unroll
    for (int s = 0; s < NSTAGE - 1; s++) { load_stage(s, s); cp_commit(); }

    // slot index trackers (avoid % in loop)
    int sCur = 0;                 // slot holding stage kt
    int sNxt = NSTAGE - 1;        // slot to fill with stage kt+2

    // ---- main loop: wait -> sync -> issue next loads -> compute ----
    #pragma unroll 1
    for (int kt = 0; kt < NKIT; kt++) {
        cp_wait1();               // group for stage kt complete (<=1 pending)
        __syncthreads();          // all warps past iter kt-1 => slot sNxt drained

        if (kt + NSTAGE - 1 < NKIT) load_stage(sNxt, kt + NSTAGE - 1);
        cp_commit();              // always commit to keep group accounting

        const uint32_t aBase = sb + sCur * STAGE_BYTES;
        const uint32_t bBase = aBase + A_STAGE_BYTES;

        #pragma unroll
        for (int q = 0; q < 4; q++) {        // 4 x k8 within the 32-wide stage
            uint32_t A[2][4], B[8][2];
            #pragma unroll
            for (int mi = 0; mi < 2; mi++)
                ldsm_x4(A[mi][0], A[mi][1], A[mi][2], A[mi][3],
                        aBase + aRow[mi] + ((((uint32_t)q << 5) | aHx) ^ xorv));
            #pragma unroll
            for (int nt = 0; nt < 4; nt++)
                ldsm_x4(B[2 * nt][0], B[2 * nt][1], B[2 * nt + 1][0], B[2 * nt + 1][1],
                        bBase + bRow[nt] + ((((uint32_t)q << 5) | bHx) ^ xorv));
            #pragma unroll
            for (int mi = 0; mi < 2; mi++)
                #pragma unroll
                for (int ni = 0; ni < 8; ni++)
                    mma_tf32(acc[mi][ni], A[mi], B[ni]);
        }

        sCur = (sCur == NSTAGE - 1) ? 0 : sCur + 1;
        sNxt = (sNxt == NSTAGE - 1) ? 0 : sNxt + 1;
    }

    // ---- epilogue: + bias, write float2 pairs ----
    const int g  = lane >> 2;     // group row
    const int tg = lane & 3;      // col pair
    #pragma unroll
    for (int mi = 0; mi < 2; mi++) {
        const int m0 = blockIdx.y * BM + wm * 32 + mi * 16 + g;
        #pragma unroll
        for (int ni = 0; ni < 8; ni++) {
            const int n = blockIdx.x * BN + wn * 64 + ni * 8 + tg * 2;
            float2 bv = *reinterpret_cast<const float2*>(bias + n);
            float2 v0 = { acc[mi][ni][0] + bv.x, acc[mi][ni][1] + bv.y };
            float2 v1 = { acc[mi][ni][2] + bv.x, acc[mi][ni][3] + bv.y };
            *reinterpret_cast<float2*>(out + (size_t)m0 * N_TOTAL + n) = v0;
            *reinterpret_cast<float2*>(out + (size_t)(m0 + 8) * N_TOTAL + n) = v1;
        }
    }
}

// ============================================================================
// Launch (graph-capturable: kernel launches only)
// ============================================================================
extern "C" void kernel_launch(void* const* d_in, const int* in_sizes, int n_in,
                              void* d_out, int out_size) {
    const float* x         = (const float*)d_in[0];   // 4*2048*4096 f32
    const float* centroids = (const float*)d_in[1];   // 256 f32
    const int*   labels    = (const int*)d_in[2];     // 4096*4096 i32
    const float* bias      = (const float*)d_in[3];   // 4096 f32
    float* out = (float*)d_out;                       // 8192*4096 f32

    cudaFuncSetAttribute(gemm_kernel, cudaFuncAttributeMaxDynamicSharedMemorySize,
                         SMEM_BYTES);

    dequant_kernel<<<(N_TOTAL * K_TOTAL) / 1024, 256>>>(centroids, labels);
    cvt_x_kernel<<<(M_TOTAL * K_TOTAL) / 1024, 256>>>(x);
    gemm_kernel<<<dim3(N_TOTAL / BN, M_TOTAL / BM), THREADS, SMEM_BYTES>>>(bias, out);
}